// round 16
// baseline (speedup 1.0000x reference)
#include <cuda_runtime.h>
#include <cuda_fp16.h>
#include <math.h>
#include <stdint.h>

#define N_TOK 4096
#define DIM   128
#define NH    8
#define HD    (NH*DIM)   // 1024

// ---------------------------------------------------------------------------
// Global scratch (fp16 hi/lo splits everywhere on the GEMM path)
// ---------------------------------------------------------------------------
__device__ __align__(128) __half g_xhi[(size_t)N_TOK * DIM];
__device__ __align__(128) __half g_xlo[(size_t)N_TOK * DIM];
__device__ __align__(128) __half g_Wqh[(size_t)NH * DIM * DIM];
__device__ __align__(128) __half g_Wql[(size_t)NH * DIM * DIM];
__device__ __align__(128) __half g_Wkh[(size_t)NH * DIM * DIM];
__device__ __align__(128) __half g_Wkl[(size_t)NH * DIM * DIM];
__device__ __align__(128) __half g_Wvh[(size_t)NH * DIM * DIM];
__device__ __align__(128) __half g_Wvl[(size_t)NH * DIM * DIM];
__device__ __align__(128) __half g_Woh[(size_t)HD * DIM];
__device__ __align__(128) __half g_Wol[(size_t)HD * DIM];

__device__ __align__(128) __half g_qhi[(size_t)NH * N_TOK * DIM];
__device__ __align__(128) __half g_qlo[(size_t)NH * N_TOK * DIM];
__device__ __align__(128) __half g_khi[(size_t)NH * N_TOK * DIM];
__device__ __align__(128) __half g_klo[(size_t)NH * N_TOK * DIM];
__device__ __align__(128) __half g_vhi[(size_t)NH * N_TOK * DIM];
__device__ __align__(128) __half g_vlo[(size_t)NH * N_TOK * DIM];
__device__ __align__(128) __half g_ahi[(size_t)N_TOK * HD];   // attn out hi
__device__ __align__(128) __half g_alo[(size_t)N_TOK * HD];   // attn out lo

// ---------------------------------------------------------------------------
// helpers
// ---------------------------------------------------------------------------
__device__ __forceinline__ uint32_t smem_u32(const void* p) {
    uint32_t a;
    asm("{ .reg .u64 t; cvta.to.shared.u64 t, %1; cvt.u32.u64 %0, t; }"
        : "=r"(a) : "l"(p));
    return a;
}
__device__ __forceinline__ void ldsm_x4(uint32_t* r, uint32_t addr) {
    asm volatile("ldmatrix.sync.aligned.m8n8.x4.shared.b16 {%0,%1,%2,%3}, [%4];"
        : "=r"(r[0]), "=r"(r[1]), "=r"(r[2]), "=r"(r[3]) : "r"(addr));
}
__device__ __forceinline__ void ldsm_x4_t(uint32_t* r, uint32_t addr) {
    asm volatile("ldmatrix.sync.aligned.m8n8.x4.trans.shared.b16 {%0,%1,%2,%3}, [%4];"
        : "=r"(r[0]), "=r"(r[1]), "=r"(r[2]), "=r"(r[3]) : "r"(addr));
}
__device__ __forceinline__ void mma_f32(float* c, const uint32_t* a,
                                        uint32_t b0, uint32_t b1) {
    asm volatile("mma.sync.aligned.m16n8k16.row.col.f32.f16.f16.f32 "
        "{%0,%1,%2,%3}, {%4,%5,%6,%7}, {%8,%9}, {%0,%1,%2,%3};"
        : "+f"(c[0]), "+f"(c[1]), "+f"(c[2]), "+f"(c[3])
        : "r"(a[0]), "r"(a[1]), "r"(a[2]), "r"(a[3]), "r"(b0), "r"(b1));
}
__device__ __forceinline__ uint32_t pack2h(float a, float b) {
    __half2 h = __floats2half2_rn(a, b);
    return *(uint32_t*)&h;
}
__device__ __forceinline__ void split2(float a, float b, uint32_t* hi, uint32_t* lo) {
    __half ha = __float2half_rn(a), hb = __float2half_rn(b);
    *hi = (uint32_t)*(unsigned short*)&ha | ((uint32_t)*(unsigned short*)&hb << 16);
    *lo = pack2h(a - __half2float(ha), b - __half2float(hb));
}
#define CP_ASYNC16(s, g) \
    asm volatile("cp.async.cg.shared.global [%0], [%1], 16;" :: "r"(s), "l"(g))
#define CP_COMMIT() asm volatile("cp.async.commit_group;" ::: "memory")
#define CP_WAIT0()  asm volatile("cp.async.wait_group 0;" ::: "memory")
#define CP_WAIT1()  asm volatile("cp.async.wait_group 1;" ::: "memory")

// ---------------------------------------------------------------------------
// Split kernel: fp32 -> fp16 hi/lo for x, Wq, Wk, Wv, Wo
// ---------------------------------------------------------------------------
#define XS  (N_TOK*DIM)          // 524288
#define WS  (NH*DIM*DIM)         // 131072
__global__ __launch_bounds__(256) void split_kernel(
    const float* __restrict__ x,  const float* __restrict__ Wq,
    const float* __restrict__ Wk, const float* __restrict__ Wv,
    const float* __restrict__ Wo)
{
    int i = (blockIdx.x * 256 + threadIdx.x) * 4;
    const float* src; __half *dh, *dl; int off;
    if (i < XS)                 { src = x;  dh = g_xhi; dl = g_xlo; off = 0; }
    else if (i < XS + WS)       { src = Wq; dh = g_Wqh; dl = g_Wql; off = XS; }
    else if (i < XS + 2*WS)     { src = Wk; dh = g_Wkh; dl = g_Wkl; off = XS + WS; }
    else if (i < XS + 3*WS)     { src = Wv; dh = g_Wvh; dl = g_Wvl; off = XS + 2*WS; }
    else                        { src = Wo; dh = g_Woh; dl = g_Wol; off = XS + 3*WS; }
    int k = i - off;
    float4 v = *(const float4*)&src[k];
    uint32_t h0, l0, h1, l1;
    split2(v.x, v.y, &h0, &l0);
    split2(v.z, v.w, &h1, &l1);
    *(uint2*)&dh[k] = make_uint2(h0, h1);
    *(uint2*)&dl[k] = make_uint2(l0, l1);
}

// ---------------------------------------------------------------------------
// Projection GEMM (tensor): C[h] = x @ W[h] + b[h], 3-term fp16 split.
// ---------------------------------------------------------------------------
#define ROWB 272
#define PJ_XH 0
#define PJ_XL 34816
#define PJ_WH 69632
#define PJ_WL 104448
#define SMEM_PROJ 139264

__global__ __launch_bounds__(256, 1) void proj_mma_kernel(
    const float* __restrict__ bq, const float* __restrict__ bk,
    const float* __restrict__ bv)
{
    extern __shared__ __align__(128) char sm[];
    const uint32_t sb = smem_u32(sm);
    const int tid = threadIdx.x, warp = tid >> 5, lane = tid & 31;
    const int gid = lane >> 2, tg = lane & 3;
    const int i0 = blockIdx.x * 128, h = blockIdx.y, z = blockIdx.z;

    const uint4* wh; const uint4* wl; const float* bb;
    __half *dsth, *dstl;
    if (z == 0)      { wh = (const uint4*)g_Wqh; wl = (const uint4*)g_Wql;
                       bb = bq; dsth = g_qhi; dstl = g_qlo; }
    else if (z == 1) { wh = (const uint4*)g_Wkh; wl = (const uint4*)g_Wkl;
                       bb = bk; dsth = g_khi; dstl = g_klo; }
    else             { wh = (const uint4*)g_Wvh; wl = (const uint4*)g_Wvl;
                       bb = bv; dsth = g_vhi; dstl = g_vlo; }
    bb += h * DIM;

    const uint4* xh = (const uint4*)g_xhi;
    const uint4* xl = (const uint4*)g_xlo;

    #pragma unroll
    for (int it = 0; it < 8; ++it) {
        int idx = tid + it * 256;
        int row = idx >> 4, c = idx & 15;
        int so = row * ROWB + c * 16;
        *(uint4*)(sm + PJ_XH + so) = xh[(size_t)(i0 + row) * 16 + c];
        *(uint4*)(sm + PJ_XL + so) = xl[(size_t)(i0 + row) * 16 + c];
        *(uint4*)(sm + PJ_WH + so) = wh[(size_t)h * 2048 + row * 16 + c];
        *(uint4*)(sm + PJ_WL + so) = wl[(size_t)h * 2048 + row * 16 + c];
    }
    __syncthreads();

    const int a_row = warp * 16 + (lane & 15);
    const int a_ch  = (lane >> 4) * 8;
    const int t_kr  = (lane & 7) + ((lane >> 3) & 1) * 8;
    const int t_nc  = ((lane >> 4) & 1) * 8;

    float acc[16][4];
    #pragma unroll
    for (int n = 0; n < 16; ++n)
        #pragma unroll
        for (int u = 0; u < 4; ++u) acc[n][u] = 0.f;

    #pragma unroll
    for (int ks = 0; ks < 8; ++ks) {
        uint32_t ah[4], al[4];
        uint32_t va = a_row * ROWB + (ks * 16 + a_ch) * 2;
        ldsm_x4(ah, sb + PJ_XH + va);
        ldsm_x4(al, sb + PJ_XL + va);
        #pragma unroll
        for (int n16 = 0; n16 < 8; ++n16) {
            uint32_t bh[4], bl[4];
            uint32_t wa = (ks * 16 + t_kr) * ROWB + (n16 * 16 + t_nc) * 2;
            ldsm_x4_t(bh, sb + PJ_WH + wa);
            ldsm_x4_t(bl, sb + PJ_WL + wa);
            mma_f32(acc[2*n16],   ah, bh[0], bh[1]);
            mma_f32(acc[2*n16],   ah, bl[0], bl[1]);
            mma_f32(acc[2*n16],   al, bh[0], bh[1]);
            mma_f32(acc[2*n16+1], ah, bh[2], bh[3]);
            mma_f32(acc[2*n16+1], ah, bl[2], bl[3]);
            mma_f32(acc[2*n16+1], al, bh[2], bh[3]);
        }
    }

    int r0 = i0 + warp * 16 + gid;
    int r1 = r0 + 8;
    size_t base0 = ((size_t)h * N_TOK + r0) * DIM;
    size_t base1 = ((size_t)h * N_TOK + r1) * DIM;
    #pragma unroll
    for (int n = 0; n < 16; ++n) {
        int col = n * 8 + tg * 2;
        float b0 = bb[col], b1 = bb[col + 1];
        uint32_t h0, l0, h1, l1;
        split2(acc[n][0] + b0, acc[n][1] + b1, &h0, &l0);
        split2(acc[n][2] + b0, acc[n][3] + b1, &h1, &l1);
        *(uint32_t*)&dsth[base0 + col] = h0;
        *(uint32_t*)&dstl[base0 + col] = l0;
        *(uint32_t*)&dsth[base1 + col] = h1;
        *(uint32_t*)&dstl[base1 + col] = l1;
    }
}

// ---------------------------------------------------------------------------
// Flash attention via mma.sync, fp16 hi/lo split, f32 accum.
// 256-row CTA, 8 warps x 32-row stripes, 32-token j-tiles. Online-max softmax.
// VOTE-GATED RESCALE: when the running max is unchanged for every row owned
// by the warp (sc == 1.0 exactly, the common case after early iterations),
// skip the 128-multiply O-rescale + lrow multiply. Bitwise-identical math.
// S = 3-term split; O = P(fp16) x K_hi single term. cp.async prefetch.
// ---------------------------------------------------------------------------
#define OFF_VH 0                 // 256 rows hi (69632)
#define OFF_VL 69632             // 256 rows lo
#define OFF_Q  139264            // + buf*17408 ; QH at +0, QL at +8704
#define OFF_K  174080            // + buf*8704  ; KH only
#define SMEM_DYN 191488

__global__ __launch_bounds__(256, 1) void attn_mma_kernel()
{
    extern __shared__ __align__(128) char sm[];
    const uint32_t sb = smem_u32(sm);

    const int tid  = threadIdx.x;
    const int warp = tid >> 5;
    const int lane = tid & 31;
    const int gid  = lane >> 2;
    const int tg   = lane & 3;
    const int h    = blockIdx.y;
    const int i0   = blockIdx.x * 256;

    const uint4* qh = (const uint4*)g_qhi;
    const uint4* ql = (const uint4*)g_qlo;
    const uint4* kh = (const uint4*)g_khi;
    const uint4* vh = (const uint4*)g_vhi;
    const uint4* vl = (const uint4*)g_vlo;

    #pragma unroll
    for (int it = 0; it < 16; ++it) {
        int idx = tid + it * 256;
        int row = idx >> 4, c = idx & 15;
        int so = row * ROWB + c * 16;
        size_t g = ((size_t)h * N_TOK + i0 + row) * 16 + c;
        *(uint4*)(sm + OFF_VH + so) = vh[g];
        *(uint4*)(sm + OFF_VL + so) = vl[g];
    }
    #pragma unroll
    for (int it = 0; it < 2; ++it) {
        int idx = tid + it * 256;
        int row = idx >> 4, c = idx & 15;
        int so = row * ROWB + c * 16;
        size_t g = ((size_t)h * N_TOK + row) * 16 + c;
        *(uint4*)(sm + OFF_Q + so)        = qh[g];
        *(uint4*)(sm + OFF_Q + 8704 + so) = ql[g];
        *(uint4*)(sm + OFF_K + so)        = kh[g];
    }
    __syncthreads();

    const int a_row = warp * 32 + (lane & 15);
    const int a_ch  = (lane >> 4) * 8;
    const int b_tok = (lane & 7) + ((lane >> 4) & 1) * 8;
    const int b_kh  = ((lane >> 3) & 1) * 8;
    const int t_kr  = (lane & 7) + ((lane >> 3) & 1) * 8;
    const int t_nc  = ((lane >> 4) & 1) * 8;

    float ot[2][16][4];
    #pragma unroll
    for (int m = 0; m < 2; ++m)
        #pragma unroll
        for (int n = 0; n < 16; ++n)
            #pragma unroll
            for (int u = 0; u < 4; ++u) ot[m][n][u] = 0.f;
    float mrow[2][2] = {{-INFINITY, -INFINITY}, {-INFINITY, -INFINITY}};
    float lrow[2][2] = {{0.f, 0.f}, {0.f, 0.f}};

    #pragma unroll 1
    for (int j = 0; j < 128; ++j) {
        if (j < 127) {
            int j0n = (j + 1) * 32;
            uint32_t qb = sb + OFF_Q + ((j + 1) & 1) * 17408;
            uint32_t kb = sb + OFF_K + ((j + 1) & 1) * 8704;
            #pragma unroll
            for (int it = 0; it < 2; ++it) {
                int idx = tid + it * 256;
                int row = idx >> 4, c = idx & 15;
                int so = row * ROWB + c * 16;
                size_t g = ((size_t)h * N_TOK + j0n + row) * 16 + c;
                CP_ASYNC16(qb + so,        qh + g);
                CP_ASYNC16(qb + 8704 + so, ql + g);
                CP_ASYNC16(kb + so,        kh + g);
            }
            CP_COMMIT();
        }

        const uint32_t qbh = sb + OFF_Q + (j & 1) * 17408;
        const uint32_t qbl = qbh + 8704;
        const uint32_t kbh = sb + OFF_K + (j & 1) * 8704;

        float st[2][4][4];
        #pragma unroll
        for (int m = 0; m < 2; ++m)
            #pragma unroll
            for (int n = 0; n < 4; ++n)
                #pragma unroll
                for (int u = 0; u < 4; ++u) st[m][n][u] = 0.f;

        #pragma unroll
        for (int ks = 0; ks < 8; ++ks) {
            uint32_t avh[2][4], avl[2][4];
            #pragma unroll
            for (int m = 0; m < 2; ++m) {
                uint32_t va = (a_row + m * 16) * ROWB + (ks * 16 + a_ch) * 2;
                ldsm_x4(avh[m], sb + OFF_VH + va);
                ldsm_x4(avl[m], sb + OFF_VL + va);
            }
            #pragma unroll
            for (int nt2 = 0; nt2 < 2; ++nt2) {
                uint32_t bqh[4], bql[4];
                uint32_t qa = (nt2 * 16 + b_tok) * ROWB + (ks * 16 + b_kh) * 2;
                ldsm_x4(bqh, qbh + qa);
                ldsm_x4(bql, qbl + qa);
                #pragma unroll
                for (int m = 0; m < 2; ++m) {
                    mma_f32(st[m][2*nt2],   avh[m], bqh[0], bqh[1]);
                    mma_f32(st[m][2*nt2],   avh[m], bql[0], bql[1]);
                    mma_f32(st[m][2*nt2],   avl[m], bqh[0], bqh[1]);
                    mma_f32(st[m][2*nt2+1], avh[m], bqh[2], bqh[3]);
                    mma_f32(st[m][2*nt2+1], avh[m], bql[2], bql[3]);
                    mma_f32(st[m][2*nt2+1], avl[m], bqh[2], bqh[3]);
                }
            }
        }

        uint32_t ph[2][2][4];
        float sc[2][2];
        #pragma unroll
        for (int m = 0; m < 2; ++m) {
            float mx0 = st[m][0][0], mx1 = st[m][0][2];
            #pragma unroll
            for (int n = 0; n < 4; ++n) {
                mx0 = fmaxf(mx0, fmaxf(st[m][n][0], st[m][n][1]));
                mx1 = fmaxf(mx1, fmaxf(st[m][n][2], st[m][n][3]));
            }
            mx0 = fmaxf(mx0, __shfl_xor_sync(0xffffffffu, mx0, 1));
            mx0 = fmaxf(mx0, __shfl_xor_sync(0xffffffffu, mx0, 2));
            mx1 = fmaxf(mx1, __shfl_xor_sync(0xffffffffu, mx1, 1));
            mx1 = fmaxf(mx1, __shfl_xor_sync(0xffffffffu, mx1, 2));
            float mn0 = fmaxf(mrow[m][0], mx0), mn1 = fmaxf(mrow[m][1], mx1);
            sc[m][0] = __expf(mrow[m][0] - mn0);
            sc[m][1] = __expf(mrow[m][1] - mn1);
            mrow[m][0] = mn0; mrow[m][1] = mn1;
            float sum0 = 0.f, sum1 = 0.f;
            #pragma unroll
            for (int n = 0; n < 4; ++n) {
                st[m][n][0] = __expf(st[m][n][0] - mn0); sum0 += st[m][n][0];
                st[m][n][1] = __expf(st[m][n][1] - mn0); sum0 += st[m][n][1];
                st[m][n][2] = __expf(st[m][n][2] - mn1); sum1 += st[m][n][2];
                st[m][n][3] = __expf(st[m][n][3] - mn1); sum1 += st[m][n][3];
            }
            sum0 += __shfl_xor_sync(0xffffffffu, sum0, 1);
            sum0 += __shfl_xor_sync(0xffffffffu, sum0, 2);
            sum1 += __shfl_xor_sync(0xffffffffu, sum1, 1);
            sum1 += __shfl_xor_sync(0xffffffffu, sum1, 2);
            lrow[m][0] = lrow[m][0] * sc[m][0] + sum0;
            lrow[m][1] = lrow[m][1] * sc[m][1] + sum1;
            #pragma unroll
            for (int ks2 = 0; ks2 < 2; ++ks2) {
                #pragma unroll
                for (int half = 0; half < 2; ++half) {
                    int n = 2 * ks2 + half;
                    ph[m][ks2][2*half+0] = pack2h(st[m][n][0], st[m][n][1]);
                    ph[m][ks2][2*half+1] = pack2h(st[m][n][2], st[m][n][3]);
                }
            }
        }

        // vote-gated O rescale: skip 128 multiplies when all scales are 1.0
        bool need = (sc[0][0] != 1.f) | (sc[0][1] != 1.f)
                  | (sc[1][0] != 1.f) | (sc[1][1] != 1.f);
        if (__any_sync(0xffffffffu, need)) {
            #pragma unroll
            for (int m = 0; m < 2; ++m)
                #pragma unroll
                for (int n = 0; n < 16; ++n) {
                    ot[m][n][0] *= sc[m][0]; ot[m][n][1] *= sc[m][0];
                    ot[m][n][2] *= sc[m][1]; ot[m][n][3] *= sc[m][1];
                }
        }

        #pragma unroll
        for (int ks2 = 0; ks2 < 2; ++ks2) {
            #pragma unroll
            for (int pp = 0; pp < 4; ++pp) {
                uint32_t bh0[4], bh1[4];
                uint32_t ka0 = (ks2 * 16 + t_kr) * ROWB + ((2*pp) * 16 + t_nc) * 2;
                uint32_t ka1 = ka0 + 32;
                ldsm_x4_t(bh0, kbh + ka0);
                ldsm_x4_t(bh1, kbh + ka1);
                #pragma unroll
                for (int m = 0; m < 2; ++m) {
                    mma_f32(ot[m][4*pp+0], ph[m][ks2], bh0[0], bh0[1]);
                    mma_f32(ot[m][4*pp+1], ph[m][ks2], bh0[2], bh0[3]);
                    mma_f32(ot[m][4*pp+2], ph[m][ks2], bh1[0], bh1[1]);
                    mma_f32(ot[m][4*pp+3], ph[m][ks2], bh1[2], bh1[3]);
                }
            }
        }

        if (j < 127) CP_WAIT0();
        __syncthreads();
    }

    #pragma unroll
    for (int m = 0; m < 2; ++m) {
        float inv0 = 1.f / lrow[m][0], inv1 = 1.f / lrow[m][1];
        int r0 = i0 + warp * 32 + m * 16 + gid;
        int r1 = r0 + 8;
        #pragma unroll
        for (int n = 0; n < 16; ++n) {
            int col = h * 128 + n * 8 + tg * 2;
            uint32_t h0, lo0, h1, lo1;
            split2(ot[m][n][0] * inv0, ot[m][n][1] * inv0, &h0, &lo0);
            split2(ot[m][n][2] * inv1, ot[m][n][3] * inv1, &h1, &lo1);
            *(uint32_t*)&g_ahi[(size_t)r0 * HD + col] = h0;
            *(uint32_t*)&g_alo[(size_t)r0 * HD + col] = lo0;
            *(uint32_t*)&g_ahi[(size_t)r1 * HD + col] = h1;
            *(uint32_t*)&g_alo[(size_t)r1 * HD + col] = lo1;
        }
    }
}

// ---------------------------------------------------------------------------
// Output GEMM (tensor): out = attn @ Wo + bo. 128 CTAs x 32 rows; 8 warps =
// 2 row-stripes x 4 col-quarters. cp.async double-buffered A/W k-tiles.
// ---------------------------------------------------------------------------
#define OG_A   0                 // + buf*87040 ; AH at +0,  AL at +8704
#define OG_W   17408             // + buf*87040 ; WH at +0,  WL at +34816
#define OG_BUF 87040
#define SMEM_OUT 174080

__global__ __launch_bounds__(256, 1) void out_mma_kernel(
    const float* __restrict__ bo, float* __restrict__ out)
{
    extern __shared__ __align__(128) char sm[];
    const uint32_t sb = smem_u32(sm);
    const int tid = threadIdx.x, warp = tid >> 5, lane = tid & 31;
    const int gid = lane >> 2, tg = lane & 3;
    const int wr = warp >> 2, wc = warp & 3;
    const int i0 = blockIdx.x * 32;

    const uint4* ah4 = (const uint4*)g_ahi;
    const uint4* al4 = (const uint4*)g_alo;
    const uint4* wh4 = (const uint4*)g_Woh;
    const uint4* wl4 = (const uint4*)g_Wol;

    const int a_row = wr * 16 + (lane & 15);
    const int a_ch  = (lane >> 4) * 8;
    const int t_kr  = (lane & 7) + ((lane >> 3) & 1) * 8;
    const int t_nc  = ((lane >> 4) & 1) * 8;

    {
        uint32_t ab = sb + OG_A, wb = sb + OG_W;
        #pragma unroll
        for (int it = 0; it < 2; ++it) {
            int idx = tid + it * 256;
            int row = idx >> 4, c = idx & 15;
            int so = row * ROWB + c * 16;
            size_t g = (size_t)(i0 + row) * 128 + c;
            CP_ASYNC16(ab + so,        ah4 + g);
            CP_ASYNC16(ab + 8704 + so, al4 + g);
        }
        #pragma unroll
        for (int it = 0; it < 8; ++it) {
            int idx = tid + it * 256;
            int row = idx >> 4, c = idx & 15;
            int so = row * ROWB + c * 16;
            size_t g = (size_t)row * 16 + c;
            CP_ASYNC16(wb + so,         wh4 + g);
            CP_ASYNC16(wb + 34816 + so, wl4 + g);
        }
        CP_COMMIT();
    }

    float acc[8][4];
    #pragma unroll
    for (int n = 0; n < 8; ++n)
        #pragma unroll
        for (int u = 0; u < 4; ++u) acc[n][u] = 0.f;

    #pragma unroll 1
    for (int kt = 0; kt < 8; ++kt) {
        if (kt < 7) {
            uint32_t ab = sb + OG_A + ((kt + 1) & 1) * OG_BUF;
            uint32_t wb = sb + OG_W + ((kt + 1) & 1) * OG_BUF;
            #pragma unroll
            for (int it = 0; it < 2; ++it) {
                int idx = tid + it * 256;
                int row = idx >> 4, c = idx & 15;
                int so = row * ROWB + c * 16;
                size_t g = (size_t)(i0 + row) * 128 + (kt + 1) * 16 + c;
                CP_ASYNC16(ab + so,        ah4 + g);
                CP_ASYNC16(ab + 8704 + so, al4 + g);
            }
            #pragma unroll
            for (int it = 0; it < 8; ++it) {
                int idx = tid + it * 256;
                int row = idx >> 4, c = idx & 15;
                int so = row * ROWB + c * 16;
                size_t g = (size_t)((kt + 1) * 128 + row) * 16 + c;
                CP_ASYNC16(wb + so,         wh4 + g);
                CP_ASYNC16(wb + 34816 + so, wl4 + g);
            }
            CP_COMMIT();
            CP_WAIT1();
        } else {
            CP_WAIT0();
        }
        __syncthreads();

        const uint32_t abh = sb + OG_A + (kt & 1) * OG_BUF;
        const uint32_t abl = abh + 8704;
        const uint32_t wbh = sb + OG_W + (kt & 1) * OG_BUF;
        const uint32_t wbl = wbh + 34816;

        #pragma unroll
        for (int ks = 0; ks < 8; ++ks) {
            uint32_t ah[4], al[4];
            uint32_t va = a_row * ROWB + (ks * 16 + a_ch) * 2;
            ldsm_x4(ah, abh + va);
            ldsm_x4(al, abl + va);
            #pragma unroll
            for (int n16 = 0; n16 < 2; ++n16) {
                uint32_t bh[4], bl[4];
                uint32_t wa = (ks * 16 + t_kr) * ROWB
                            + (wc * 32 + n16 * 16 + t_nc) * 2;
                ldsm_x4_t(bh, wbh + wa);
                ldsm_x4_t(bl, wbl + wa);
                mma_f32(acc[2*n16],   ah, bh[0], bh[1]);
                mma_f32(acc[2*n16],   ah, bl[0], bl[1]);
                mma_f32(acc[2*n16],   al, bh[0], bh[1]);
                mma_f32(acc[2*n16+1], ah, bh[2], bh[3]);
                mma_f32(acc[2*n16+1], ah, bl[2], bl[3]);
                mma_f32(acc[2*n16+1], al, bh[2], bh[3]);
            }
        }
        __syncthreads();
    }

    int r0 = i0 + wr * 16 + gid;
    int r1 = r0 + 8;
    #pragma unroll
    for (int n = 0; n < 4; ++n) {
        int col = wc * 32 + n * 8 + tg * 2;
        float b0 = bo[col], b1 = bo[col + 1];
        *(float2*)&out[(size_t)r0 * DIM + col] =
            make_float2(acc[n][0] + b0, acc[n][1] + b1);
        *(float2*)&out[(size_t)r1 * DIM + col] =
            make_float2(acc[n][2] + b0, acc[n][3] + b1);
    }
}

// ---------------------------------------------------------------------------
extern "C" void kernel_launch(void* const* d_in, const int* in_sizes, int n_in,
                              void* d_out, int out_size)
{
    const float* x  = (const float*)d_in[0];
    const float* Wq = (const float*)d_in[1];
    const float* bq = (const float*)d_in[2];
    const float* Wk = (const float*)d_in[3];
    const float* bk = (const float*)d_in[4];
    const float* Wv = (const float*)d_in[5];
    const float* bv = (const float*)d_in[6];
    const float* Wo = (const float*)d_in[7];
    const float* bo = (const float*)d_in[8];
    float* out = (float*)d_out;

    cudaFuncSetAttribute(proj_mma_kernel,
                         cudaFuncAttributeMaxDynamicSharedMemorySize, SMEM_PROJ);
    cudaFuncSetAttribute(attn_mma_kernel,
                         cudaFuncAttributeMaxDynamicSharedMemorySize, SMEM_DYN);
    cudaFuncSetAttribute(out_mma_kernel,
                         cudaFuncAttributeMaxDynamicSharedMemorySize, SMEM_OUT);

    split_kernel<<<1024, 256>>>(x, Wq, Wk, Wv, Wo);

    dim3 gp(N_TOK/128, NH, 3);
    proj_mma_kernel<<<gp, 256, SMEM_PROJ>>>(bq, bk, bv);

    dim3 g2(N_TOK/256, NH);
    attn_mma_kernel<<<g2, 256, SMEM_DYN>>>();

    out_mma_kernel<<<N_TOK/32, 256, SMEM_OUT>>>(bo, out);
}

// round 17
// speedup vs baseline: 1.0325x; 1.0325x over previous
#include <cuda_runtime.h>
#include <cuda_fp16.h>
#include <math.h>
#include <stdint.h>

#define N_TOK 4096
#define DIM   128
#define NH    8
#define HD    (NH*DIM)   // 1024

// ---------------------------------------------------------------------------
// Global scratch (fp16 hi/lo splits everywhere on the GEMM path)
// ---------------------------------------------------------------------------
__device__ __align__(128) __half g_xhi[(size_t)N_TOK * DIM];
__device__ __align__(128) __half g_xlo[(size_t)N_TOK * DIM];
__device__ __align__(128) __half g_Wqh[(size_t)NH * DIM * DIM];
__device__ __align__(128) __half g_Wql[(size_t)NH * DIM * DIM];
__device__ __align__(128) __half g_Wkh[(size_t)NH * DIM * DIM];
__device__ __align__(128) __half g_Wkl[(size_t)NH * DIM * DIM];
__device__ __align__(128) __half g_Wvh[(size_t)NH * DIM * DIM];
__device__ __align__(128) __half g_Wvl[(size_t)NH * DIM * DIM];
__device__ __align__(128) __half g_Woh[(size_t)HD * DIM];
__device__ __align__(128) __half g_Wol[(size_t)HD * DIM];

__device__ __align__(128) __half g_qhi[(size_t)NH * N_TOK * DIM];
__device__ __align__(128) __half g_qlo[(size_t)NH * N_TOK * DIM];
__device__ __align__(128) __half g_khi[(size_t)NH * N_TOK * DIM];
__device__ __align__(128) __half g_klo[(size_t)NH * N_TOK * DIM];
__device__ __align__(128) __half g_vhi[(size_t)NH * N_TOK * DIM];
__device__ __align__(128) __half g_vlo[(size_t)NH * N_TOK * DIM];
__device__ __align__(128) __half g_ahi[(size_t)N_TOK * HD];   // attn out hi
__device__ __align__(128) __half g_alo[(size_t)N_TOK * HD];   // attn out lo

// ---------------------------------------------------------------------------
// helpers
// ---------------------------------------------------------------------------
__device__ __forceinline__ uint32_t smem_u32(const void* p) {
    uint32_t a;
    asm("{ .reg .u64 t; cvta.to.shared.u64 t, %1; cvt.u32.u64 %0, t; }"
        : "=r"(a) : "l"(p));
    return a;
}
__device__ __forceinline__ void ldsm_x4(uint32_t* r, uint32_t addr) {
    asm volatile("ldmatrix.sync.aligned.m8n8.x4.shared.b16 {%0,%1,%2,%3}, [%4];"
        : "=r"(r[0]), "=r"(r[1]), "=r"(r[2]), "=r"(r[3]) : "r"(addr));
}
__device__ __forceinline__ void ldsm_x4_t(uint32_t* r, uint32_t addr) {
    asm volatile("ldmatrix.sync.aligned.m8n8.x4.trans.shared.b16 {%0,%1,%2,%3}, [%4];"
        : "=r"(r[0]), "=r"(r[1]), "=r"(r[2]), "=r"(r[3]) : "r"(addr));
}
__device__ __forceinline__ void mma_f32(float* c, const uint32_t* a,
                                        uint32_t b0, uint32_t b1) {
    asm volatile("mma.sync.aligned.m16n8k16.row.col.f32.f16.f16.f32 "
        "{%0,%1,%2,%3}, {%4,%5,%6,%7}, {%8,%9}, {%0,%1,%2,%3};"
        : "+f"(c[0]), "+f"(c[1]), "+f"(c[2]), "+f"(c[3])
        : "r"(a[0]), "r"(a[1]), "r"(a[2]), "r"(a[3]), "r"(b0), "r"(b1));
}
__device__ __forceinline__ uint32_t pack2h(float a, float b) {
    __half2 h = __floats2half2_rn(a, b);
    return *(uint32_t*)&h;
}
__device__ __forceinline__ void split2(float a, float b, uint32_t* hi, uint32_t* lo) {
    __half ha = __float2half_rn(a), hb = __float2half_rn(b);
    *hi = (uint32_t)*(unsigned short*)&ha | ((uint32_t)*(unsigned short*)&hb << 16);
    *lo = pack2h(a - __half2float(ha), b - __half2float(hb));
}
#define CP_ASYNC16(s, g) \
    asm volatile("cp.async.cg.shared.global [%0], [%1], 16;" :: "r"(s), "l"(g))
#define CP_COMMIT() asm volatile("cp.async.commit_group;" ::: "memory")
#define CP_WAIT0()  asm volatile("cp.async.wait_group 0;" ::: "memory")
#define CP_WAIT1()  asm volatile("cp.async.wait_group 1;" ::: "memory")

// ---------------------------------------------------------------------------
// Split kernel: fp32 -> fp16 hi/lo for x, Wq, Wk, Wv, Wo
// ---------------------------------------------------------------------------
#define XS  (N_TOK*DIM)          // 524288
#define WS  (NH*DIM*DIM)         // 131072
__global__ __launch_bounds__(256) void split_kernel(
    const float* __restrict__ x,  const float* __restrict__ Wq,
    const float* __restrict__ Wk, const float* __restrict__ Wv,
    const float* __restrict__ Wo)
{
    int i = (blockIdx.x * 256 + threadIdx.x) * 4;
    const float* src; __half *dh, *dl; int off;
    if (i < XS)                 { src = x;  dh = g_xhi; dl = g_xlo; off = 0; }
    else if (i < XS + WS)       { src = Wq; dh = g_Wqh; dl = g_Wql; off = XS; }
    else if (i < XS + 2*WS)     { src = Wk; dh = g_Wkh; dl = g_Wkl; off = XS + WS; }
    else if (i < XS + 3*WS)     { src = Wv; dh = g_Wvh; dl = g_Wvl; off = XS + 2*WS; }
    else                        { src = Wo; dh = g_Woh; dl = g_Wol; off = XS + 3*WS; }
    int k = i - off;
    float4 v = *(const float4*)&src[k];
    uint32_t h0, l0, h1, l1;
    split2(v.x, v.y, &h0, &l0);
    split2(v.z, v.w, &h1, &l1);
    *(uint2*)&dh[k] = make_uint2(h0, h1);
    *(uint2*)&dl[k] = make_uint2(l0, l1);
}

// ---------------------------------------------------------------------------
// Projection GEMM (tensor): C[h] = x @ W[h] + b[h], 3-term fp16 split.
// ---------------------------------------------------------------------------
#define ROWB 272
#define PJ_XH 0
#define PJ_XL 34816
#define PJ_WH 69632
#define PJ_WL 104448
#define SMEM_PROJ 139264

__global__ __launch_bounds__(256, 1) void proj_mma_kernel(
    const float* __restrict__ bq, const float* __restrict__ bk,
    const float* __restrict__ bv)
{
    extern __shared__ __align__(128) char sm[];
    const uint32_t sb = smem_u32(sm);
    const int tid = threadIdx.x, warp = tid >> 5, lane = tid & 31;
    const int gid = lane >> 2, tg = lane & 3;
    const int i0 = blockIdx.x * 128, h = blockIdx.y, z = blockIdx.z;

    const uint4* wh; const uint4* wl; const float* bb;
    __half *dsth, *dstl;
    if (z == 0)      { wh = (const uint4*)g_Wqh; wl = (const uint4*)g_Wql;
                       bb = bq; dsth = g_qhi; dstl = g_qlo; }
    else if (z == 1) { wh = (const uint4*)g_Wkh; wl = (const uint4*)g_Wkl;
                       bb = bk; dsth = g_khi; dstl = g_klo; }
    else             { wh = (const uint4*)g_Wvh; wl = (const uint4*)g_Wvl;
                       bb = bv; dsth = g_vhi; dstl = g_vlo; }
    bb += h * DIM;

    const uint4* xh = (const uint4*)g_xhi;
    const uint4* xl = (const uint4*)g_xlo;

    #pragma unroll
    for (int it = 0; it < 8; ++it) {
        int idx = tid + it * 256;
        int row = idx >> 4, c = idx & 15;
        int so = row * ROWB + c * 16;
        *(uint4*)(sm + PJ_XH + so) = xh[(size_t)(i0 + row) * 16 + c];
        *(uint4*)(sm + PJ_XL + so) = xl[(size_t)(i0 + row) * 16 + c];
        *(uint4*)(sm + PJ_WH + so) = wh[(size_t)h * 2048 + row * 16 + c];
        *(uint4*)(sm + PJ_WL + so) = wl[(size_t)h * 2048 + row * 16 + c];
    }
    __syncthreads();

    const int a_row = warp * 16 + (lane & 15);
    const int a_ch  = (lane >> 4) * 8;
    const int t_kr  = (lane & 7) + ((lane >> 3) & 1) * 8;
    const int t_nc  = ((lane >> 4) & 1) * 8;

    float acc[16][4];
    #pragma unroll
    for (int n = 0; n < 16; ++n)
        #pragma unroll
        for (int u = 0; u < 4; ++u) acc[n][u] = 0.f;

    #pragma unroll
    for (int ks = 0; ks < 8; ++ks) {
        uint32_t ah[4], al[4];
        uint32_t va = a_row * ROWB + (ks * 16 + a_ch) * 2;
        ldsm_x4(ah, sb + PJ_XH + va);
        ldsm_x4(al, sb + PJ_XL + va);
        #pragma unroll
        for (int n16 = 0; n16 < 8; ++n16) {
            uint32_t bh[4], bl[4];
            uint32_t wa = (ks * 16 + t_kr) * ROWB + (n16 * 16 + t_nc) * 2;
            ldsm_x4_t(bh, sb + PJ_WH + wa);
            ldsm_x4_t(bl, sb + PJ_WL + wa);
            mma_f32(acc[2*n16],   ah, bh[0], bh[1]);
            mma_f32(acc[2*n16],   ah, bl[0], bl[1]);
            mma_f32(acc[2*n16],   al, bh[0], bh[1]);
            mma_f32(acc[2*n16+1], ah, bh[2], bh[3]);
            mma_f32(acc[2*n16+1], ah, bl[2], bl[3]);
            mma_f32(acc[2*n16+1], al, bh[2], bh[3]);
        }
    }

    int r0 = i0 + warp * 16 + gid;
    int r1 = r0 + 8;
    size_t base0 = ((size_t)h * N_TOK + r0) * DIM;
    size_t base1 = ((size_t)h * N_TOK + r1) * DIM;
    #pragma unroll
    for (int n = 0; n < 16; ++n) {
        int col = n * 8 + tg * 2;
        float b0 = bb[col], b1 = bb[col + 1];
        uint32_t h0, l0, h1, l1;
        split2(acc[n][0] + b0, acc[n][1] + b1, &h0, &l0);
        split2(acc[n][2] + b0, acc[n][3] + b1, &h1, &l1);
        *(uint32_t*)&dsth[base0 + col] = h0;
        *(uint32_t*)&dstl[base0 + col] = l0;
        *(uint32_t*)&dsth[base1 + col] = h1;
        *(uint32_t*)&dstl[base1 + col] = l1;
    }
}

// ---------------------------------------------------------------------------
// Flash attention via mma.sync, fp16 hi/lo split, f32 accum.
// 256-row CTA, 8 warps x 32-row stripes, 32-token j-tiles. Online-max softmax
// (fp16 P requires it -- fixed-offset overflows fp16). Unconditional rescale
// (round 16 showed it is latency-hidden; gating it REGRESSED).
// S = 3-term split; O = P(fp16) x K_hi single term. cp.async prefetch.
// ---------------------------------------------------------------------------
#define OFF_VH 0                 // 256 rows hi (69632)
#define OFF_VL 69632             // 256 rows lo
#define OFF_Q  139264            // + buf*17408 ; QH at +0, QL at +8704
#define OFF_K  174080            // + buf*8704  ; KH only
#define SMEM_DYN 191488

__global__ __launch_bounds__(256, 1) void attn_mma_kernel()
{
    extern __shared__ __align__(128) char sm[];
    const uint32_t sb = smem_u32(sm);

    const int tid  = threadIdx.x;
    const int warp = tid >> 5;
    const int lane = tid & 31;
    const int gid  = lane >> 2;
    const int tg   = lane & 3;
    const int h    = blockIdx.y;
    const int i0   = blockIdx.x * 256;

    const uint4* qh = (const uint4*)g_qhi;
    const uint4* ql = (const uint4*)g_qlo;
    const uint4* kh = (const uint4*)g_khi;
    const uint4* vh = (const uint4*)g_vhi;
    const uint4* vl = (const uint4*)g_vlo;

    #pragma unroll
    for (int it = 0; it < 16; ++it) {
        int idx = tid + it * 256;
        int row = idx >> 4, c = idx & 15;
        int so = row * ROWB + c * 16;
        size_t g = ((size_t)h * N_TOK + i0 + row) * 16 + c;
        *(uint4*)(sm + OFF_VH + so) = vh[g];
        *(uint4*)(sm + OFF_VL + so) = vl[g];
    }
    #pragma unroll
    for (int it = 0; it < 2; ++it) {
        int idx = tid + it * 256;
        int row = idx >> 4, c = idx & 15;
        int so = row * ROWB + c * 16;
        size_t g = ((size_t)h * N_TOK + row) * 16 + c;
        *(uint4*)(sm + OFF_Q + so)        = qh[g];
        *(uint4*)(sm + OFF_Q + 8704 + so) = ql[g];
        *(uint4*)(sm + OFF_K + so)        = kh[g];
    }
    __syncthreads();

    const int a_row = warp * 32 + (lane & 15);
    const int a_ch  = (lane >> 4) * 8;
    const int b_tok = (lane & 7) + ((lane >> 4) & 1) * 8;
    const int b_kh  = ((lane >> 3) & 1) * 8;
    const int t_kr  = (lane & 7) + ((lane >> 3) & 1) * 8;
    const int t_nc  = ((lane >> 4) & 1) * 8;

    float ot[2][16][4];
    #pragma unroll
    for (int m = 0; m < 2; ++m)
        #pragma unroll
        for (int n = 0; n < 16; ++n)
            #pragma unroll
            for (int u = 0; u < 4; ++u) ot[m][n][u] = 0.f;
    float mrow[2][2] = {{-INFINITY, -INFINITY}, {-INFINITY, -INFINITY}};
    float lrow[2][2] = {{0.f, 0.f}, {0.f, 0.f}};

    #pragma unroll 1
    for (int j = 0; j < 128; ++j) {
        if (j < 127) {
            int j0n = (j + 1) * 32;
            uint32_t qb = sb + OFF_Q + ((j + 1) & 1) * 17408;
            uint32_t kb = sb + OFF_K + ((j + 1) & 1) * 8704;
            #pragma unroll
            for (int it = 0; it < 2; ++it) {
                int idx = tid + it * 256;
                int row = idx >> 4, c = idx & 15;
                int so = row * ROWB + c * 16;
                size_t g = ((size_t)h * N_TOK + j0n + row) * 16 + c;
                CP_ASYNC16(qb + so,        qh + g);
                CP_ASYNC16(qb + 8704 + so, ql + g);
                CP_ASYNC16(kb + so,        kh + g);
            }
            CP_COMMIT();
        }

        const uint32_t qbh = sb + OFF_Q + (j & 1) * 17408;
        const uint32_t qbl = qbh + 8704;
        const uint32_t kbh = sb + OFF_K + (j & 1) * 8704;

        float st[2][4][4];
        #pragma unroll
        for (int m = 0; m < 2; ++m)
            #pragma unroll
            for (int n = 0; n < 4; ++n)
                #pragma unroll
                for (int u = 0; u < 4; ++u) st[m][n][u] = 0.f;

        #pragma unroll
        for (int ks = 0; ks < 8; ++ks) {
            uint32_t avh[2][4], avl[2][4];
            #pragma unroll
            for (int m = 0; m < 2; ++m) {
                uint32_t va = (a_row + m * 16) * ROWB + (ks * 16 + a_ch) * 2;
                ldsm_x4(avh[m], sb + OFF_VH + va);
                ldsm_x4(avl[m], sb + OFF_VL + va);
            }
            #pragma unroll
            for (int nt2 = 0; nt2 < 2; ++nt2) {
                uint32_t bqh[4], bql[4];
                uint32_t qa = (nt2 * 16 + b_tok) * ROWB + (ks * 16 + b_kh) * 2;
                ldsm_x4(bqh, qbh + qa);
                ldsm_x4(bql, qbl + qa);
                #pragma unroll
                for (int m = 0; m < 2; ++m) {
                    mma_f32(st[m][2*nt2],   avh[m], bqh[0], bqh[1]);
                    mma_f32(st[m][2*nt2],   avh[m], bql[0], bql[1]);
                    mma_f32(st[m][2*nt2],   avl[m], bqh[0], bqh[1]);
                    mma_f32(st[m][2*nt2+1], avh[m], bqh[2], bqh[3]);
                    mma_f32(st[m][2*nt2+1], avh[m], bql[2], bql[3]);
                    mma_f32(st[m][2*nt2+1], avl[m], bqh[2], bqh[3]);
                }
            }
        }

        uint32_t ph[2][2][4];
        #pragma unroll
        for (int m = 0; m < 2; ++m) {
            float mx0 = st[m][0][0], mx1 = st[m][0][2];
            #pragma unroll
            for (int n = 0; n < 4; ++n) {
                mx0 = fmaxf(mx0, fmaxf(st[m][n][0], st[m][n][1]));
                mx1 = fmaxf(mx1, fmaxf(st[m][n][2], st[m][n][3]));
            }
            mx0 = fmaxf(mx0, __shfl_xor_sync(0xffffffffu, mx0, 1));
            mx0 = fmaxf(mx0, __shfl_xor_sync(0xffffffffu, mx0, 2));
            mx1 = fmaxf(mx1, __shfl_xor_sync(0xffffffffu, mx1, 1));
            mx1 = fmaxf(mx1, __shfl_xor_sync(0xffffffffu, mx1, 2));
            float mn0 = fmaxf(mrow[m][0], mx0), mn1 = fmaxf(mrow[m][1], mx1);
            float sc0 = __expf(mrow[m][0] - mn0), sc1 = __expf(mrow[m][1] - mn1);
            mrow[m][0] = mn0; mrow[m][1] = mn1;
            float sum0 = 0.f, sum1 = 0.f;
            #pragma unroll
            for (int n = 0; n < 4; ++n) {
                st[m][n][0] = __expf(st[m][n][0] - mn0); sum0 += st[m][n][0];
                st[m][n][1] = __expf(st[m][n][1] - mn0); sum0 += st[m][n][1];
                st[m][n][2] = __expf(st[m][n][2] - mn1); sum1 += st[m][n][2];
                st[m][n][3] = __expf(st[m][n][3] - mn1); sum1 += st[m][n][3];
            }
            sum0 += __shfl_xor_sync(0xffffffffu, sum0, 1);
            sum0 += __shfl_xor_sync(0xffffffffu, sum0, 2);
            sum1 += __shfl_xor_sync(0xffffffffu, sum1, 1);
            sum1 += __shfl_xor_sync(0xffffffffu, sum1, 2);
            lrow[m][0] = lrow[m][0] * sc0 + sum0;
            lrow[m][1] = lrow[m][1] * sc1 + sum1;
            #pragma unroll
            for (int n = 0; n < 16; ++n) {
                ot[m][n][0] *= sc0; ot[m][n][1] *= sc0;
                ot[m][n][2] *= sc1; ot[m][n][3] *= sc1;
            }
            #pragma unroll
            for (int ks2 = 0; ks2 < 2; ++ks2) {
                #pragma unroll
                for (int half = 0; half < 2; ++half) {
                    int n = 2 * ks2 + half;
                    ph[m][ks2][2*half+0] = pack2h(st[m][n][0], st[m][n][1]);
                    ph[m][ks2][2*half+1] = pack2h(st[m][n][2], st[m][n][3]);
                }
            }
        }

        #pragma unroll
        for (int ks2 = 0; ks2 < 2; ++ks2) {
            #pragma unroll
            for (int pp = 0; pp < 4; ++pp) {
                uint32_t bh0[4], bh1[4];
                uint32_t ka0 = (ks2 * 16 + t_kr) * ROWB + ((2*pp) * 16 + t_nc) * 2;
                uint32_t ka1 = ka0 + 32;
                ldsm_x4_t(bh0, kbh + ka0);
                ldsm_x4_t(bh1, kbh + ka1);
                #pragma unroll
                for (int m = 0; m < 2; ++m) {
                    mma_f32(ot[m][4*pp+0], ph[m][ks2], bh0[0], bh0[1]);
                    mma_f32(ot[m][4*pp+1], ph[m][ks2], bh0[2], bh0[3]);
                    mma_f32(ot[m][4*pp+2], ph[m][ks2], bh1[0], bh1[1]);
                    mma_f32(ot[m][4*pp+3], ph[m][ks2], bh1[2], bh1[3]);
                }
            }
        }

        if (j < 127) CP_WAIT0();
        __syncthreads();
    }

    #pragma unroll
    for (int m = 0; m < 2; ++m) {
        float inv0 = 1.f / lrow[m][0], inv1 = 1.f / lrow[m][1];
        int r0 = i0 + warp * 32 + m * 16 + gid;
        int r1 = r0 + 8;
        #pragma unroll
        for (int n = 0; n < 16; ++n) {
            int col = h * 128 + n * 8 + tg * 2;
            uint32_t h0, lo0, h1, lo1;
            split2(ot[m][n][0] * inv0, ot[m][n][1] * inv0, &h0, &lo0);
            split2(ot[m][n][2] * inv1, ot[m][n][3] * inv1, &h1, &lo1);
            *(uint32_t*)&g_ahi[(size_t)r0 * HD + col] = h0;
            *(uint32_t*)&g_alo[(size_t)r0 * HD + col] = lo0;
            *(uint32_t*)&g_ahi[(size_t)r1 * HD + col] = h1;
            *(uint32_t*)&g_alo[(size_t)r1 * HD + col] = lo1;
        }
    }
}

// ---------------------------------------------------------------------------
// Output GEMM (tensor): out = attn @ Wo + bo. 128 CTAs x 32 rows; 8 warps =
// 2 row-stripes x 4 col-quarters. cp.async double-buffered A/W k-tiles.
// ---------------------------------------------------------------------------
#define OG_A   0                 // + buf*87040 ; AH at +0,  AL at +8704
#define OG_W   17408             // + buf*87040 ; WH at +0,  WL at +34816
#define OG_BUF 87040
#define SMEM_OUT 174080

__global__ __launch_bounds__(256, 1) void out_mma_kernel(
    const float* __restrict__ bo, float* __restrict__ out)
{
    extern __shared__ __align__(128) char sm[];
    const uint32_t sb = smem_u32(sm);
    const int tid = threadIdx.x, warp = tid >> 5, lane = tid & 31;
    const int gid = lane >> 2, tg = lane & 3;
    const int wr = warp >> 2, wc = warp & 3;
    const int i0 = blockIdx.x * 32;

    const uint4* ah4 = (const uint4*)g_ahi;
    const uint4* al4 = (const uint4*)g_alo;
    const uint4* wh4 = (const uint4*)g_Woh;
    const uint4* wl4 = (const uint4*)g_Wol;

    const int a_row = wr * 16 + (lane & 15);
    const int a_ch  = (lane >> 4) * 8;
    const int t_kr  = (lane & 7) + ((lane >> 3) & 1) * 8;
    const int t_nc  = ((lane >> 4) & 1) * 8;

    {
        uint32_t ab = sb + OG_A, wb = sb + OG_W;
        #pragma unroll
        for (int it = 0; it < 2; ++it) {
            int idx = tid + it * 256;
            int row = idx >> 4, c = idx & 15;
            int so = row * ROWB + c * 16;
            size_t g = (size_t)(i0 + row) * 128 + c;
            CP_ASYNC16(ab + so,        ah4 + g);
            CP_ASYNC16(ab + 8704 + so, al4 + g);
        }
        #pragma unroll
        for (int it = 0; it < 8; ++it) {
            int idx = tid + it * 256;
            int row = idx >> 4, c = idx & 15;
            int so = row * ROWB + c * 16;
            size_t g = (size_t)row * 16 + c;
            CP_ASYNC16(wb + so,         wh4 + g);
            CP_ASYNC16(wb + 34816 + so, wl4 + g);
        }
        CP_COMMIT();
    }

    float acc[8][4];
    #pragma unroll
    for (int n = 0; n < 8; ++n)
        #pragma unroll
        for (int u = 0; u < 4; ++u) acc[n][u] = 0.f;

    #pragma unroll 1
    for (int kt = 0; kt < 8; ++kt) {
        if (kt < 7) {
            uint32_t ab = sb + OG_A + ((kt + 1) & 1) * OG_BUF;
            uint32_t wb = sb + OG_W + ((kt + 1) & 1) * OG_BUF;
            #pragma unroll
            for (int it = 0; it < 2; ++it) {
                int idx = tid + it * 256;
                int row = idx >> 4, c = idx & 15;
                int so = row * ROWB + c * 16;
                size_t g = (size_t)(i0 + row) * 128 + (kt + 1) * 16 + c;
                CP_ASYNC16(ab + so,        ah4 + g);
                CP_ASYNC16(ab + 8704 + so, al4 + g);
            }
            #pragma unroll
            for (int it = 0; it < 8; ++it) {
                int idx = tid + it * 256;
                int row = idx >> 4, c = idx & 15;
                int so = row * ROWB + c * 16;
                size_t g = (size_t)((kt + 1) * 128 + row) * 16 + c;
                CP_ASYNC16(wb + so,         wh4 + g);
                CP_ASYNC16(wb + 34816 + so, wl4 + g);
            }
            CP_COMMIT();
            CP_WAIT1();
        } else {
            CP_WAIT0();
        }
        __syncthreads();

        const uint32_t abh = sb + OG_A + (kt & 1) * OG_BUF;
        const uint32_t abl = abh + 8704;
        const uint32_t wbh = sb + OG_W + (kt & 1) * OG_BUF;
        const uint32_t wbl = wbh + 34816;

        #pragma unroll
        for (int ks = 0; ks < 8; ++ks) {
            uint32_t ah[4], al[4];
            uint32_t va = a_row * ROWB + (ks * 16 + a_ch) * 2;
            ldsm_x4(ah, abh + va);
            ldsm_x4(al, abl + va);
            #pragma unroll
            for (int n16 = 0; n16 < 2; ++n16) {
                uint32_t bh[4], bl[4];
                uint32_t wa = (ks * 16 + t_kr) * ROWB
                            + (wc * 32 + n16 * 16 + t_nc) * 2;
                ldsm_x4_t(bh, wbh + wa);
                ldsm_x4_t(bl, wbl + wa);
                mma_f32(acc[2*n16],   ah, bh[0], bh[1]);
                mma_f32(acc[2*n16],   ah, bl[0], bl[1]);
                mma_f32(acc[2*n16],   al, bh[0], bh[1]);
                mma_f32(acc[2*n16+1], ah, bh[2], bh[3]);
                mma_f32(acc[2*n16+1], ah, bl[2], bl[3]);
                mma_f32(acc[2*n16+1], al, bh[2], bh[3]);
            }
        }
        __syncthreads();
    }

    int r0 = i0 + wr * 16 + gid;
    int r1 = r0 + 8;
    #pragma unroll
    for (int n = 0; n < 4; ++n) {
        int col = wc * 32 + n * 8 + tg * 2;
        float b0 = bo[col], b1 = bo[col + 1];
        *(float2*)&out[(size_t)r0 * DIM + col] =
            make_float2(acc[n][0] + b0, acc[n][1] + b1);
        *(float2*)&out[(size_t)r1 * DIM + col] =
            make_float2(acc[n][2] + b0, acc[n][3] + b1);
    }
}

// ---------------------------------------------------------------------------
extern "C" void kernel_launch(void* const* d_in, const int* in_sizes, int n_in,
                              void* d_out, int out_size)
{
    const float* x  = (const float*)d_in[0];
    const float* Wq = (const float*)d_in[1];
    const float* bq = (const float*)d_in[2];
    const float* Wk = (const float*)d_in[3];
    const float* bk = (const float*)d_in[4];
    const float* Wv = (const float*)d_in[5];
    const float* bv = (const float*)d_in[6];
    const float* Wo = (const float*)d_in[7];
    const float* bo = (const float*)d_in[8];
    float* out = (float*)d_out;

    cudaFuncSetAttribute(proj_mma_kernel,
                         cudaFuncAttributeMaxDynamicSharedMemorySize, SMEM_PROJ);
    cudaFuncSetAttribute(attn_mma_kernel,
                         cudaFuncAttributeMaxDynamicSharedMemorySize, SMEM_DYN);
    cudaFuncSetAttribute(out_mma_kernel,
                         cudaFuncAttributeMaxDynamicSharedMemorySize, SMEM_OUT);

    split_kernel<<<1024, 256>>>(x, Wq, Wk, Wv, Wo);

    dim3 gp(N_TOK/128, NH, 3);
    proj_mma_kernel<<<gp, 256, SMEM_PROJ>>>(bq, bk, bv);

    dim3 g2(N_TOK/256, NH);
    attn_mma_kernel<<<g2, 256, SMEM_DYN>>>();

    out_mma_kernel<<<N_TOK/32, 256, SMEM_OUT>>>(bo, out);
}